// round 11
// baseline (speedup 1.0000x reference)
#include <cuda_runtime.h>
#include <cuda_bf16.h>
#include <cstdint>

#define NUM_NODES 100000
#define NUM_EDGES 50000
#define INC 12
#define N_EDGE_TILES 196   // ceil(50000/256)
#define N_NODE_TILES 391   // ceil(100000/256)

// Scratch:
__device__ __align__(16) float g_yd[(size_t)NUM_NODES * 128];   // x(Ws-Wh)^T + bs + bh
__device__ __align__(16) float g_zsum[(size_t)NUM_EDGES * 128]; // (sum_e x)·Wh^T
// bf16 hi/lo weight images: [0:16384)=Wd=(Ws-Wh), [16384:32768)=Wh  (row n, col k)
__device__ __align__(16) __nv_bfloat16 g_bhi[2 * 16384];
__device__ __align__(16) __nv_bfloat16 g_blo[2 * 16384];
__device__ __align__(16) float g_bias[128];

__device__ __forceinline__ uint32_t smem_u32(const void* p) {
    uint32_t a;
    asm("{ .reg .u64 t; cvta.to.shared.u64 t, %1; cvt.u32.u64 %0, t; }" : "=r"(a) : "l"(p));
    return a;
}
__device__ __forceinline__ void ldmx4(uint32_t* r, uint32_t addr) {
    asm volatile("ldmatrix.sync.aligned.m8n8.x4.shared.b16 {%0,%1,%2,%3}, [%4];"
        : "=r"(r[0]), "=r"(r[1]), "=r"(r[2]), "=r"(r[3]) : "r"(addr));
}
__device__ __forceinline__ void mma_bf16(float* c, const uint32_t* a, const uint32_t* b) {
    asm volatile("mma.sync.aligned.m16n8k16.row.col.f32.bf16.bf16.f32 "
        "{%0,%1,%2,%3}, {%4,%5,%6,%7}, {%8,%9}, {%0,%1,%2,%3};"
        : "+f"(c[0]), "+f"(c[1]), "+f"(c[2]), "+f"(c[3])
        : "r"(a[0]), "r"(a[1]), "r"(a[2]), "r"(a[3]), "r"(b[0]), "r"(b[1]));
}
__device__ __forceinline__ uint32_t bpack(float e0, float e1) {  // e0 -> low half
    uint32_t r;
    asm("cvt.rn.bf16x2.f32 %0, %1, %2;" : "=r"(r) : "f"(e1), "f"(e0));
    return r;
}
// Split a float4 into bf16 hi/lo packed pairs
__device__ __forceinline__ void split4(float4 v, uint2& hi, uint2& lo) {
    __nv_bfloat16 h0 = __float2bfloat16_rn(v.x), h1 = __float2bfloat16_rn(v.y);
    __nv_bfloat16 h2 = __float2bfloat16_rn(v.z), h3 = __float2bfloat16_rn(v.w);
    hi.x = ((uint32_t)__bfloat16_as_ushort(h1) << 16) | __bfloat16_as_ushort(h0);
    hi.y = ((uint32_t)__bfloat16_as_ushort(h3) << 16) | __bfloat16_as_ushort(h2);
    lo.x = bpack(v.x - __bfloat162float(h0), v.y - __bfloat162float(h1));
    lo.y = bpack(v.z - __bfloat162float(h2), v.w - __bfloat162float(h3));
}

// SMEM: padded row stride 272 B (ldmatrix conflict-free, 16B-aligned rows)
#define STRB 272
#define SM_AHI 0
#define SM_ALO (256 * STRB)              // 69632
#define SM_BHI (2 * 256 * STRB)          // 139264
#define SM_BLO (SM_BHI + 128 * STRB)     // 174080
#define SM_TOTAL (SM_BLO + 128 * STRB)   // 208896

// ---------------------------------------------------------------------------
// Kernel 0: weights -> bf16 hi/lo images + fused bias
// ---------------------------------------------------------------------------
__global__ void prep_kernel(const float* __restrict__ Ws, const float* __restrict__ bs,
                            const float* __restrict__ Wh, const float* __restrict__ bh) {
    int idx = blockIdx.x * blockDim.x + threadIdx.x;   // 0..32767
    int img = idx >> 14, n = (idx >> 7) & 127, k = idx & 127;
    float v = img ? Wh[n * 128 + k] : (Ws[n * 128 + k] - Wh[n * 128 + k]);
    __nv_bfloat16 hi = __float2bfloat16_rn(v);
    g_bhi[idx] = hi;
    g_blo[idx] = __float2bfloat16_rn(v - __bfloat162float(hi));
    if (idx < 128) g_bias[idx] = bs[idx] + bh[idx];
}

// ---------------------------------------------------------------------------
// Kernel 1: merged split-bf16 mma.sync GEMM, 587 heterogeneous CTAs.
//   blockIdx <  196: EDGE tile — A row e = sum of 12 incident x rows (fused
//                    xsum gather), B = Wh, out = g_zsum, bias = 0.
//   blockIdx >= 196: NODE tile — A row = x row, B = Ws-Wh, out = g_yd, +bias.
// CTA tile M=256 x N=128, K=128. D = Ahi*Bhi + Ahi*Blo + Alo*Bhi (fp32 acc).
// Edge tiles first: heaviest CTAs start earliest for wave balance.
// ---------------------------------------------------------------------------
__global__ void __launch_bounds__(256, 1) mma_kernel(
    const float* __restrict__ x, const int* __restrict__ node_ids) {
    extern __shared__ char smem[];
    const uint32_t sb = smem_u32(smem);
    const int tid = threadIdx.x;
    const bool is_edge = blockIdx.x < N_EDGE_TILES;
    const int m0 = (is_edge ? blockIdx.x : blockIdx.x - N_EDGE_TILES) * 256;
    const int nrows = is_edge ? NUM_EDGES : NUM_NODES;
    float* outp = is_edge ? g_zsum : g_yd;
    const __nv_bfloat16* wbhi = g_bhi + (is_edge ? 16384 : 0);
    const __nv_bfloat16* wblo = g_blo + (is_edge ? 16384 : 0);

    // ---- A fill
    if (is_edge) {
        // warp-per-row gather: sum 12 x rows in fp32, split bf16, store smem
        const int w = tid >> 5, lane = tid & 31;
        #pragma unroll 2
        for (int it = 0; it < 32; it++) {
            int rloc = it * 8 + w;
            int e = m0 + rloc;
            float4 s = make_float4(0.f, 0.f, 0.f, 0.f);
            if (e < NUM_EDGES) {
                const int4* ids4 = (const int4*)(node_ids + e * INC);
                int4 i0 = __ldg(ids4 + 0), i1 = __ldg(ids4 + 1), i2 = __ldg(ids4 + 2);
                int ids[INC] = {i0.x, i0.y, i0.z, i0.w, i1.x, i1.y, i1.z, i1.w,
                                i2.x, i2.y, i2.z, i2.w};
                #pragma unroll
                for (int i = 0; i < INC; i++) {
                    float4 v = __ldg(((const float4*)(x + (size_t)ids[i] * 128)) + lane);
                    s.x += v.x; s.y += v.y; s.z += v.z; s.w += v.w;
                }
            }
            uint2 hi, lo;
            split4(s, hi, lo);
            uint32_t off = (uint32_t)rloc * STRB + lane * 8;
            *(uint2*)(smem + SM_AHI + off) = hi;
            *(uint2*)(smem + SM_ALO + off) = lo;
        }
    } else {
        #pragma unroll
        for (int it = 0; it < 32; it++) {
            int idx = tid + 256 * it;
            int row = idx >> 5, c4 = idx & 31;
            int gm = m0 + row;
            float4 v = make_float4(0.f, 0.f, 0.f, 0.f);
            if (gm < NUM_NODES)
                v = __ldg(((const float4*)(x + (size_t)gm * 128)) + c4);
            uint2 hi, lo;
            split4(v, hi, lo);
            uint32_t off = (uint32_t)row * STRB + c4 * 8;
            *(uint2*)(smem + SM_AHI + off) = hi;
            *(uint2*)(smem + SM_ALO + off) = lo;
        }
    }

    // ---- B fill: 128 rows x 16 chunks per image
    #pragma unroll
    for (int it = 0; it < 8; it++) {
        int idx = tid + 256 * it;            // 0..2047
        int row = idx >> 4, ch = idx & 15;
        uint32_t off = (uint32_t)row * STRB + ch * 16;
        *(uint4*)(smem + SM_BHI + off) = __ldg(((const uint4*)wbhi) + idx);
        *(uint4*)(smem + SM_BLO + off) = __ldg(((const uint4*)wblo) + idx);
    }
    __syncthreads();

    const int w = tid >> 5, lane = tid & 31;
    const int wm = w * 32;
    const int g = lane >> 3, r = lane & 7;
    const int arow = r + ((g & 1) << 3), acolb = ((g >> 1) << 3) * 2;  // A: m0-7/m8-15 x k0/k8
    const int brow = r + ((g >> 1) << 3), bcolb = ((g & 1) << 3) * 2;  // B: n0-7/n8-15 x k0/k8

    #pragma unroll
    for (int nh = 0; nh < 2; nh++) {
        const int nbase = nh * 64;
        float acc[2][8][4];
        #pragma unroll
        for (int mt = 0; mt < 2; mt++)
            #pragma unroll
            for (int nf = 0; nf < 8; nf++)
                #pragma unroll
                for (int c = 0; c < 4; c++) acc[mt][nf][c] = 0.f;

        #pragma unroll
        for (int kk = 0; kk < 8; kk++) {
            uint32_t ahi[2][4], alo[2][4];
            #pragma unroll
            for (int mt = 0; mt < 2; mt++) {
                uint32_t aa = sb + SM_AHI + (uint32_t)(wm + mt * 16 + arow) * STRB
                            + kk * 32 + acolb;
                ldmx4(ahi[mt], aa);
                ldmx4(alo[mt], aa + (SM_ALO - SM_AHI));
            }
            uint32_t bhi[4][4], blo[4][4];
            #pragma unroll
            for (int nt = 0; nt < 4; nt++) {
                uint32_t ba = sb + SM_BHI + (uint32_t)(nbase + nt * 16 + brow) * STRB
                            + kk * 32 + bcolb;
                ldmx4(bhi[nt], ba);
                ldmx4(blo[nt], ba + (SM_BLO - SM_BHI));
            }
            #pragma unroll
            for (int mt = 0; mt < 2; mt++)
                #pragma unroll
                for (int nt = 0; nt < 4; nt++)
                    #pragma unroll
                    for (int h = 0; h < 2; h++) {
                        float* c = acc[mt][nt * 2 + h];
                        mma_bf16(c, ahi[mt], &bhi[nt][2 * h]);
                        mma_bf16(c, ahi[mt], &blo[nt][2 * h]);
                        mma_bf16(c, alo[mt], &bhi[nt][2 * h]);
                    }
        }

        // ---- Epilogue: bias (node tiles only) + store
        #pragma unroll
        for (int mt = 0; mt < 2; mt++) {
            int row0 = m0 + wm + mt * 16 + (lane >> 2);
            #pragma unroll
            for (int nf = 0; nf < 8; nf++) {
                int col = nbase + nf * 8 + 2 * (lane & 3);
                float2 bi = is_edge ? make_float2(0.f, 0.f)
                                    : *(const float2*)(g_bias + col);
                if (row0 < nrows) {
                    float2 o = make_float2(acc[mt][nf][0] + bi.x, acc[mt][nf][1] + bi.y);
                    *(float2*)(outp + (size_t)row0 * 128 + col) = o;
                }
                if (row0 + 8 < nrows) {
                    float2 o = make_float2(acc[mt][nf][2] + bi.x, acc[mt][nf][3] + bi.y);
                    *(float2*)(outp + (size_t)(row0 + 8) * 128 + col) = o;
                }
            }
        }
    }
}

// ---------------------------------------------------------------------------
// Kernel 2: warp-per-edge: emb_i = relu(yd_i + zsum_e), max-min pool, score.
// ---------------------------------------------------------------------------
__global__ void edge_kernel(const int* __restrict__ node_ids,
                            const float* __restrict__ w_score,
                            const float* __restrict__ b_score,
                            float* __restrict__ out) {
    int gw   = (blockIdx.x * blockDim.x + threadIdx.x) >> 5;
    int lane = threadIdx.x & 31;
    if (gw >= NUM_EDGES) return;

    const int4* ids4 = (const int4*)(node_ids + gw * INC);
    int4 i0 = __ldg(ids4 + 0), i1 = __ldg(ids4 + 1), i2 = __ldg(ids4 + 2);
    int ids[INC] = {i0.x, i0.y, i0.z, i0.w, i1.x, i1.y, i1.z, i1.w,
                    i2.x, i2.y, i2.z, i2.w};

    float4 zs = __ldg(((const float4*)(g_zsum + (size_t)gw * 128)) + lane);

    float4 mx = make_float4(-1e30f, -1e30f, -1e30f, -1e30f);
    float4 mn = make_float4( 1e30f,  1e30f,  1e30f,  1e30f);
    #pragma unroll
    for (int i = 0; i < INC; i++) {
        float4 yd = __ldg(((const float4*)(g_yd + (size_t)ids[i] * 128)) + lane);
        float vx = fmaxf(yd.x + zs.x, 0.f);
        float vy = fmaxf(yd.y + zs.y, 0.f);
        float vz = fmaxf(yd.z + zs.z, 0.f);
        float vw = fmaxf(yd.w + zs.w, 0.f);
        mx.x = fmaxf(mx.x, vx); mn.x = fminf(mn.x, vx);
        mx.y = fmaxf(mx.y, vy); mn.y = fminf(mn.y, vy);
        mx.z = fmaxf(mx.z, vz); mn.z = fminf(mn.z, vz);
        mx.w = fmaxf(mx.w, vw); mn.w = fminf(mn.w, vw);
    }

    float4 w = __ldg(((const float4*)w_score) + lane);
    float p = (mx.x - mn.x) * w.x + (mx.y - mn.y) * w.y
            + (mx.z - mn.z) * w.z + (mx.w - mn.w) * w.w;
    #pragma unroll
    for (int o = 16; o > 0; o >>= 1)
        p += __shfl_xor_sync(0xffffffffu, p, o);
    if (lane == 0) out[gw] = p + __ldg(b_score);
}

// ---------------------------------------------------------------------------
extern "C" void kernel_launch(void* const* d_in, const int* in_sizes, int n_in,
                              void* d_out, int out_size) {
    const float* x    = (const float*)d_in[0];
    const int*   hidx = (const int*)  d_in[1];   // (2, 600000): row0 = node_ids
    const float* Ws   = (const float*)d_in[2];
    const float* bs   = (const float*)d_in[3];
    const float* Wh   = (const float*)d_in[4];
    const float* bh   = (const float*)d_in[5];
    const float* Wsc  = (const float*)d_in[6];
    const float* bsc  = (const float*)d_in[7];
    float* out = (float*)d_out;

    cudaFuncSetAttribute(mma_kernel, cudaFuncAttributeMaxDynamicSharedMemorySize, SM_TOTAL);

    prep_kernel<<<128, 256>>>(Ws, bs, Wh, bh);
    mma_kernel<<<N_EDGE_TILES + N_NODE_TILES, 256, SM_TOTAL>>>(x, hidx);
    edge_kernel<<<(NUM_EDGES * 32 + 255) / 256, 256>>>(hidx, Wsc, bsc, out);
}

// round 13
// speedup vs baseline: 1.1319x; 1.1319x over previous
#include <cuda_runtime.h>
#include <cuda_bf16.h>
#include <cuda_fp16.h>
#include <cstdint>

#define NUM_NODES 100000
#define NUM_EDGES 50000
#define INC 12

// Scratch:
__device__ __align__(16) __half g_yd[(size_t)NUM_NODES * 128];   // x(Ws-Wh)^T + bias (fp16)
__device__ __align__(16) float  g_xsum[(size_t)NUM_EDGES * 128]; // per-edge sum of x rows
__device__ __align__(16) __half g_zsum[(size_t)NUM_EDGES * 128]; // xsum·Wh^T (fp16)
// bf16 hi/lo weight images: [0:16384)=Wd=(Ws-Wh), [16384:32768)=Wh  (row n, col k)
__device__ __align__(16) __nv_bfloat16 g_bhi[2 * 16384];
__device__ __align__(16) __nv_bfloat16 g_blo[2 * 16384];
__device__ __align__(16) float g_bias[128];
__device__ __align__(16) float g_zero[128];

__device__ __forceinline__ uint32_t smem_u32(const void* p) {
    uint32_t a;
    asm("{ .reg .u64 t; cvta.to.shared.u64 t, %1; cvt.u32.u64 %0, t; }" : "=r"(a) : "l"(p));
    return a;
}
__device__ __forceinline__ void ldmx4(uint32_t* r, uint32_t addr) {
    asm volatile("ldmatrix.sync.aligned.m8n8.x4.shared.b16 {%0,%1,%2,%3}, [%4];"
        : "=r"(r[0]), "=r"(r[1]), "=r"(r[2]), "=r"(r[3]) : "r"(addr));
}
__device__ __forceinline__ void mma_bf16(float* c, const uint32_t* a, const uint32_t* b) {
    asm volatile("mma.sync.aligned.m16n8k16.row.col.f32.bf16.bf16.f32 "
        "{%0,%1,%2,%3}, {%4,%5,%6,%7}, {%8,%9}, {%0,%1,%2,%3};"
        : "+f"(c[0]), "+f"(c[1]), "+f"(c[2]), "+f"(c[3])
        : "r"(a[0]), "r"(a[1]), "r"(a[2]), "r"(a[3]), "r"(b[0]), "r"(b[1]));
}
__device__ __forceinline__ uint32_t bpack(float e0, float e1) {  // e0 -> low half
    uint32_t r;
    asm("cvt.rn.bf16x2.f32 %0, %1, %2;" : "=r"(r) : "f"(e1), "f"(e0));
    return r;
}
__device__ __forceinline__ float4 h4_to_f4(uint2 u) {
    __half2 a = *(__half2*)&u.x, b = *(__half2*)&u.y;
    float2 fa = __half22float2(a), fb = __half22float2(b);
    return make_float4(fa.x, fa.y, fb.x, fb.y);
}

// SMEM: padded row stride 272 B (ldmatrix conflict-free, 16B-aligned rows)
#define STRB 272
#define SM_AHI 0
#define SM_ALO (256 * STRB)              // 69632
#define SM_BHI (2 * 256 * STRB)          // 139264
#define SM_BLO (SM_BHI + 128 * STRB)     // 174080
#define SM_TOTAL (SM_BLO + 128 * STRB)   // 208896

// ---------------------------------------------------------------------------
// Kernel 0: weights -> bf16 hi/lo images + fused bias
// ---------------------------------------------------------------------------
__global__ void prep_kernel(const float* __restrict__ Ws, const float* __restrict__ bs,
                            const float* __restrict__ Wh, const float* __restrict__ bh) {
    int idx = blockIdx.x * blockDim.x + threadIdx.x;   // 0..32767
    int img = idx >> 14, n = (idx >> 7) & 127, k = idx & 127;
    float v = img ? Wh[n * 128 + k] : (Ws[n * 128 + k] - Wh[n * 128 + k]);
    __nv_bfloat16 hi = __float2bfloat16_rn(v);
    g_bhi[idx] = hi;
    g_blo[idx] = __float2bfloat16_rn(v - __bfloat162float(hi));
    if (idx < 128) g_bias[idx] = bs[idx] + bh[idx];
}

// ---------------------------------------------------------------------------
// Kernel 1: warp-per-edge xsum_e = sum of the 12 incident x rows (fp32)
// ---------------------------------------------------------------------------
__global__ void xsum_kernel(const int* __restrict__ node_ids,
                            const float* __restrict__ x) {
    int gw   = (blockIdx.x * blockDim.x + threadIdx.x) >> 5;
    int lane = threadIdx.x & 31;
    if (gw >= NUM_EDGES) return;

    const int4* ids4 = (const int4*)(node_ids + gw * INC);
    int4 i0 = __ldg(ids4 + 0), i1 = __ldg(ids4 + 1), i2 = __ldg(ids4 + 2);
    int ids[INC] = {i0.x, i0.y, i0.z, i0.w, i1.x, i1.y, i1.z, i1.w,
                    i2.x, i2.y, i2.z, i2.w};

    float4 s = make_float4(0.f, 0.f, 0.f, 0.f);
    #pragma unroll
    for (int i = 0; i < INC; i++) {
        float4 v = __ldg(((const float4*)(x + (size_t)ids[i] * 128)) + lane);
        s.x += v.x; s.y += v.y; s.z += v.z; s.w += v.w;
    }
    ((float4*)(g_xsum + (size_t)gw * 128))[lane] = s;
}

// ---------------------------------------------------------------------------
// Kernel 2: split-bf16 mma.sync GEMM. CTA tile M=256 x N=128, K=128.
// D = Ahi*Bhi + Ahi*Blo + Alo*Bhi (fp32 accum) + bias -> fp16 out.
// ---------------------------------------------------------------------------
__global__ void __launch_bounds__(256, 1) mma_kernel(
    const float* __restrict__ in, __half* __restrict__ outp, int nrows,
    const __nv_bfloat16* __restrict__ wbhi, const __nv_bfloat16* __restrict__ wblo,
    const float* __restrict__ bias) {
    extern __shared__ char smem[];
    const uint32_t sb = smem_u32(smem);
    const int tid = threadIdx.x;
    const int m0 = blockIdx.x * 256;

    // ---- A fill: 256 rows x 32 float4, split bf16 hi/lo
    #pragma unroll
    for (int it = 0; it < 32; it++) {
        int idx = tid + 256 * it;
        int row = idx >> 5, c4 = idx & 31;
        int gm = m0 + row;
        float4 v = make_float4(0.f, 0.f, 0.f, 0.f);
        if (gm < nrows)
            v = __ldg(((const float4*)(in + (size_t)gm * 128)) + c4);
        __nv_bfloat16 h0 = __float2bfloat16_rn(v.x), h1 = __float2bfloat16_rn(v.y);
        __nv_bfloat16 h2 = __float2bfloat16_rn(v.z), h3 = __float2bfloat16_rn(v.w);
        uint32_t hi01 = ((uint32_t)__bfloat16_as_ushort(h1) << 16) | __bfloat16_as_ushort(h0);
        uint32_t hi23 = ((uint32_t)__bfloat16_as_ushort(h3) << 16) | __bfloat16_as_ushort(h2);
        uint32_t lo01 = bpack(v.x - __bfloat162float(h0), v.y - __bfloat162float(h1));
        uint32_t lo23 = bpack(v.z - __bfloat162float(h2), v.w - __bfloat162float(h3));
        uint32_t off = (uint32_t)row * STRB + c4 * 8;
        *(uint2*)(smem + SM_AHI + off) = make_uint2(hi01, hi23);
        *(uint2*)(smem + SM_ALO + off) = make_uint2(lo01, lo23);
    }

    // ---- B fill: 128 rows x 16 chunks per image
    #pragma unroll
    for (int it = 0; it < 8; it++) {
        int idx = tid + 256 * it;            // 0..2047
        int row = idx >> 4, ch = idx & 15;
        uint32_t off = (uint32_t)row * STRB + ch * 16;
        *(uint4*)(smem + SM_BHI + off) = __ldg(((const uint4*)wbhi) + idx);
        *(uint4*)(smem + SM_BLO + off) = __ldg(((const uint4*)wblo) + idx);
    }
    __syncthreads();

    const int w = tid >> 5, lane = tid & 31;
    const int wm = w * 32;
    const int g = lane >> 3, r = lane & 7;
    const int arow = r + ((g & 1) << 3), acolb = ((g >> 1) << 3) * 2;  // A: m0-7/m8-15 x k0/k8
    const int brow = r + ((g >> 1) << 3), bcolb = ((g & 1) << 3) * 2;  // B: n0-7/n8-15 x k0/k8

    #pragma unroll
    for (int nh = 0; nh < 2; nh++) {
        const int nbase = nh * 64;
        float acc[2][8][4];
        #pragma unroll
        for (int mt = 0; mt < 2; mt++)
            #pragma unroll
            for (int nf = 0; nf < 8; nf++)
                #pragma unroll
                for (int c = 0; c < 4; c++) acc[mt][nf][c] = 0.f;

        #pragma unroll
        for (int kk = 0; kk < 8; kk++) {
            uint32_t ahi[2][4], alo[2][4];
            #pragma unroll
            for (int mt = 0; mt < 2; mt++) {
                uint32_t aa = sb + SM_AHI + (uint32_t)(wm + mt * 16 + arow) * STRB
                            + kk * 32 + acolb;
                ldmx4(ahi[mt], aa);
                ldmx4(alo[mt], aa + (SM_ALO - SM_AHI));
            }
            uint32_t bhi[4][4], blo[4][4];
            #pragma unroll
            for (int nt = 0; nt < 4; nt++) {
                uint32_t ba = sb + SM_BHI + (uint32_t)(nbase + nt * 16 + brow) * STRB
                            + kk * 32 + bcolb;
                ldmx4(bhi[nt], ba);
                ldmx4(blo[nt], ba + (SM_BLO - SM_BHI));
            }
            #pragma unroll
            for (int mt = 0; mt < 2; mt++)
                #pragma unroll
                for (int nt = 0; nt < 4; nt++)
                    #pragma unroll
                    for (int h = 0; h < 2; h++) {
                        float* c = acc[mt][nt * 2 + h];
                        mma_bf16(c, ahi[mt], &bhi[nt][2 * h]);
                        mma_bf16(c, ahi[mt], &blo[nt][2 * h]);
                        mma_bf16(c, alo[mt], &bhi[nt][2 * h]);
                    }
        }

        // ---- Epilogue: bias + fp16 store (__half2, 4B aligned: col even)
        #pragma unroll
        for (int mt = 0; mt < 2; mt++) {
            int row0 = m0 + wm + mt * 16 + (lane >> 2);
            #pragma unroll
            for (int nf = 0; nf < 8; nf++) {
                int col = nbase + nf * 8 + 2 * (lane & 3);
                float2 bi = *(const float2*)(bias + col);
                if (row0 < nrows) {
                    __half2 o = __floats2half2_rn(acc[mt][nf][0] + bi.x,
                                                  acc[mt][nf][1] + bi.y);
                    *(__half2*)(outp + (size_t)row0 * 128 + col) = o;
                }
                if (row0 + 8 < nrows) {
                    __half2 o = __floats2half2_rn(acc[mt][nf][2] + bi.x,
                                                  acc[mt][nf][3] + bi.y);
                    *(__half2*)(outp + (size_t)(row0 + 8) * 128 + col) = o;
                }
            }
        }
    }
}

// ---------------------------------------------------------------------------
// Kernel 3: warp-per-edge: emb_i = relu(yd_i + zsum_e), max-min pool, score.
// fp16 yd/zsum loads (uint2 = 4 halfs per lane), fp32 compute.
// ---------------------------------------------------------------------------
__global__ void edge_kernel(const int* __restrict__ node_ids,
                            const float* __restrict__ w_score,
                            const float* __restrict__ b_score,
                            float* __restrict__ out) {
    int gw   = (blockIdx.x * blockDim.x + threadIdx.x) >> 5;
    int lane = threadIdx.x & 31;
    if (gw >= NUM_EDGES) return;

    const int4* ids4 = (const int4*)(node_ids + gw * INC);
    int4 i0 = __ldg(ids4 + 0), i1 = __ldg(ids4 + 1), i2 = __ldg(ids4 + 2);
    int ids[INC] = {i0.x, i0.y, i0.z, i0.w, i1.x, i1.y, i1.z, i1.w,
                    i2.x, i2.y, i2.z, i2.w};

    float4 zs = h4_to_f4(__ldg(((const uint2*)(g_zsum + (size_t)gw * 128)) + lane));

    float4 mx = make_float4(-1e30f, -1e30f, -1e30f, -1e30f);
    float4 mn = make_float4( 1e30f,  1e30f,  1e30f,  1e30f);
    #pragma unroll
    for (int i = 0; i < INC; i++) {
        float4 yd = h4_to_f4(__ldg(((const uint2*)(g_yd + (size_t)ids[i] * 128)) + lane));
        float vx = fmaxf(yd.x + zs.x, 0.f);
        float vy = fmaxf(yd.y + zs.y, 0.f);
        float vz = fmaxf(yd.z + zs.z, 0.f);
        float vw = fmaxf(yd.w + zs.w, 0.f);
        mx.x = fmaxf(mx.x, vx); mn.x = fminf(mn.x, vx);
        mx.y = fmaxf(mx.y, vy); mn.y = fminf(mn.y, vy);
        mx.z = fmaxf(mx.z, vz); mn.z = fminf(mn.z, vz);
        mx.w = fmaxf(mx.w, vw); mn.w = fminf(mn.w, vw);
    }

    float4 w = __ldg(((const float4*)w_score) + lane);
    float p = (mx.x - mn.x) * w.x + (mx.y - mn.y) * w.y
            + (mx.z - mn.z) * w.z + (mx.w - mn.w) * w.w;
    #pragma unroll
    for (int o = 16; o > 0; o >>= 1)
        p += __shfl_xor_sync(0xffffffffu, p, o);
    if (lane == 0) out[gw] = p + __ldg(b_score);
}

// ---------------------------------------------------------------------------
extern "C" void kernel_launch(void* const* d_in, const int* in_sizes, int n_in,
                              void* d_out, int out_size) {
    const float* x    = (const float*)d_in[0];
    const int*   hidx = (const int*)  d_in[1];   // (2, 600000): row0 = node_ids
    const float* Ws   = (const float*)d_in[2];
    const float* bs   = (const float*)d_in[3];
    const float* Wh   = (const float*)d_in[4];
    const float* bh   = (const float*)d_in[5];
    const float* Wsc  = (const float*)d_in[6];
    const float* bsc  = (const float*)d_in[7];
    float* out = (float*)d_out;

    cudaFuncSetAttribute(mma_kernel, cudaFuncAttributeMaxDynamicSharedMemorySize, SM_TOTAL);

    float *p_xsum, *p_bias, *p_zero;
    __half *p_yd, *p_zsum;
    __nv_bfloat16 *p_bhi, *p_blo;
    cudaGetSymbolAddress((void**)&p_yd,   g_yd);
    cudaGetSymbolAddress((void**)&p_xsum, g_xsum);
    cudaGetSymbolAddress((void**)&p_zsum, g_zsum);
    cudaGetSymbolAddress((void**)&p_bias, g_bias);
    cudaGetSymbolAddress((void**)&p_zero, g_zero);
    cudaGetSymbolAddress((void**)&p_bhi,  g_bhi);
    cudaGetSymbolAddress((void**)&p_blo,  g_blo);

    prep_kernel<<<128, 256>>>(Ws, bs, Wh, bh);
    xsum_kernel<<<(NUM_EDGES * 32 + 255) / 256, 256>>>(hidx, x);
    mma_kernel<<<(NUM_NODES + 255) / 256, 256, SM_TOTAL>>>(
        x, p_yd, NUM_NODES, p_bhi, p_blo, p_bias);
    mma_kernel<<<(NUM_EDGES + 255) / 256, 256, SM_TOTAL>>>(
        p_xsum, p_zsum, NUM_EDGES, p_bhi + 16384, p_blo + 16384, p_zero);
    edge_kernel<<<(NUM_EDGES * 32 + 255) / 256, 256>>>(hidx, Wsc, bsc, out);
}

// round 14
// speedup vs baseline: 1.2439x; 1.0989x over previous
#include <cuda_runtime.h>
#include <cuda_bf16.h>
#include <cuda_fp16.h>
#include <cstdint>

#define NUM_NODES 100000
#define NUM_EDGES 50000
#define INC 12
#define N_NODE_T 1563   // ceil(100000/64)
#define N_EDGE_T 782    // ceil(50000/64)

// Scratch:
__device__ __align__(16) __half g_yd[(size_t)NUM_NODES * 128];   // x(Ws-Wh)^T + bias (fp16)
__device__ __align__(16) float  g_xsum[(size_t)NUM_EDGES * 128]; // per-edge sum of x rows
__device__ __align__(16) __half g_zsum[(size_t)NUM_EDGES * 128]; // xsum·Wh^T (fp16)
// bf16 hi/lo weight images: [0:16384)=Wd=(Ws-Wh), [16384:32768)=Wh  (row n, col k)
__device__ __align__(16) __nv_bfloat16 g_bhi[2 * 16384];
__device__ __align__(16) __nv_bfloat16 g_blo[2 * 16384];
__device__ __align__(16) float g_bias[128];

__device__ __forceinline__ uint32_t smem_u32(const void* p) {
    uint32_t a;
    asm("{ .reg .u64 t; cvta.to.shared.u64 t, %1; cvt.u32.u64 %0, t; }" : "=r"(a) : "l"(p));
    return a;
}
__device__ __forceinline__ void ldmx4(uint32_t* r, uint32_t addr) {
    asm volatile("ldmatrix.sync.aligned.m8n8.x4.shared.b16 {%0,%1,%2,%3}, [%4];"
        : "=r"(r[0]), "=r"(r[1]), "=r"(r[2]), "=r"(r[3]) : "r"(addr));
}
__device__ __forceinline__ void mma_bf16(float* c, const uint32_t* a, const uint32_t* b) {
    asm volatile("mma.sync.aligned.m16n8k16.row.col.f32.bf16.bf16.f32 "
        "{%0,%1,%2,%3}, {%4,%5,%6,%7}, {%8,%9}, {%0,%1,%2,%3};"
        : "+f"(c[0]), "+f"(c[1]), "+f"(c[2]), "+f"(c[3])
        : "r"(a[0]), "r"(a[1]), "r"(a[2]), "r"(a[3]), "r"(b[0]), "r"(b[1]));
}
__device__ __forceinline__ uint32_t bpack(float e0, float e1) {  // e0 -> low half
    uint32_t r;
    asm("cvt.rn.bf16x2.f32 %0, %1, %2;" : "=r"(r) : "f"(e1), "f"(e0));
    return r;
}
__device__ __forceinline__ float4 h4_to_f4(uint2 u) {
    __half2 a = *(__half2*)&u.x, b = *(__half2*)&u.y;
    float2 fa = __half22float2(a), fb = __half22float2(b);
    return make_float4(fa.x, fa.y, fb.x, fb.y);
}

// SMEM: padded row stride 272 B (ldmatrix conflict-free, 16B-aligned rows)
// Tile M=64 x N=128: total 104448 B -> 2 CTAs/SM.
#define STRB 272
#define SM_AHI 0
#define SM_ALO (64 * STRB)               // 17408
#define SM_BHI (2 * 64 * STRB)           // 34816
#define SM_BLO (SM_BHI + 128 * STRB)     // 69632
#define SM_TOTAL (SM_BLO + 128 * STRB)   // 104448

// ---------------------------------------------------------------------------
// Kernel 0: weights -> bf16 hi/lo images + fused bias
// ---------------------------------------------------------------------------
__global__ void prep_kernel(const float* __restrict__ Ws, const float* __restrict__ bs,
                            const float* __restrict__ Wh, const float* __restrict__ bh) {
    int idx = blockIdx.x * blockDim.x + threadIdx.x;   // 0..32767
    int img = idx >> 14, n = (idx >> 7) & 127, k = idx & 127;
    float v = img ? Wh[n * 128 + k] : (Ws[n * 128 + k] - Wh[n * 128 + k]);
    __nv_bfloat16 hi = __float2bfloat16_rn(v);
    g_bhi[idx] = hi;
    g_blo[idx] = __float2bfloat16_rn(v - __bfloat162float(hi));
    if (idx < 128) g_bias[idx] = bs[idx] + bh[idx];
}

// ---------------------------------------------------------------------------
// Kernel 1: warp-per-edge xsum_e = sum of the 12 incident x rows (fp32)
// ---------------------------------------------------------------------------
__global__ void xsum_kernel(const int* __restrict__ node_ids,
                            const float* __restrict__ x) {
    int gw   = (blockIdx.x * blockDim.x + threadIdx.x) >> 5;
    int lane = threadIdx.x & 31;
    if (gw >= NUM_EDGES) return;

    const int4* ids4 = (const int4*)(node_ids + gw * INC);
    int4 i0 = __ldg(ids4 + 0), i1 = __ldg(ids4 + 1), i2 = __ldg(ids4 + 2);
    int ids[INC] = {i0.x, i0.y, i0.z, i0.w, i1.x, i1.y, i1.z, i1.w,
                    i2.x, i2.y, i2.z, i2.w};

    float4 s = make_float4(0.f, 0.f, 0.f, 0.f);
    #pragma unroll
    for (int i = 0; i < INC; i++) {
        float4 v = __ldg(((const float4*)(x + (size_t)ids[i] * 128)) + lane);
        s.x += v.x; s.y += v.y; s.z += v.z; s.w += v.w;
    }
    ((float4*)(g_xsum + (size_t)gw * 128))[lane] = s;
}

// ---------------------------------------------------------------------------
// Kernel 2: merged split-bf16 mma.sync GEMM, occ 2. CTA tile M=64 x N=128.
//   blockIdx < N_NODE_T: node tile — in=x, out=g_yd, B=Wd, +bias
//   else:                edge tile — in=g_xsum, out=g_zsum, B=Wh, bias 0
// D = Ahi*Bhi + Ahi*Blo + Alo*Bhi (fp32 accum) -> fp16 out.
// 8 warps: warp w -> rows (w&1)*32, cols (w>>1)*32 (32x32 warp tile).
// ---------------------------------------------------------------------------
__global__ void __launch_bounds__(256, 2) mma_kernel(const float* __restrict__ x) {
    extern __shared__ char smem[];
    const uint32_t sb = smem_u32(smem);
    const int tid = threadIdx.x;
    const bool is_node = blockIdx.x < N_NODE_T;
    const int m0 = (is_node ? blockIdx.x : blockIdx.x - N_NODE_T) * 64;
    const int nrows = is_node ? NUM_NODES : NUM_EDGES;
    const float* in = is_node ? x : g_xsum;
    __half* outp = is_node ? g_yd : g_zsum;
    const __nv_bfloat16* wbhi = g_bhi + (is_node ? 0 : 16384);
    const __nv_bfloat16* wblo = g_blo + (is_node ? 0 : 16384);

    // ---- A fill: 64 rows x 32 float4 (2048 over 8 iters), split bf16 hi/lo
    #pragma unroll
    for (int it = 0; it < 8; it++) {
        int idx = tid + 256 * it;
        int row = idx >> 5, c4 = idx & 31;
        int gm = m0 + row;
        float4 v = make_float4(0.f, 0.f, 0.f, 0.f);
        if (gm < nrows)
            v = __ldg(((const float4*)(in + (size_t)gm * 128)) + c4);
        __nv_bfloat16 h0 = __float2bfloat16_rn(v.x), h1 = __float2bfloat16_rn(v.y);
        __nv_bfloat16 h2 = __float2bfloat16_rn(v.z), h3 = __float2bfloat16_rn(v.w);
        uint32_t hi01 = ((uint32_t)__bfloat16_as_ushort(h1) << 16) | __bfloat16_as_ushort(h0);
        uint32_t hi23 = ((uint32_t)__bfloat16_as_ushort(h3) << 16) | __bfloat16_as_ushort(h2);
        uint32_t lo01 = bpack(v.x - __bfloat162float(h0), v.y - __bfloat162float(h1));
        uint32_t lo23 = bpack(v.z - __bfloat162float(h2), v.w - __bfloat162float(h3));
        uint32_t off = (uint32_t)row * STRB + c4 * 8;
        *(uint2*)(smem + SM_AHI + off) = make_uint2(hi01, hi23);
        *(uint2*)(smem + SM_ALO + off) = make_uint2(lo01, lo23);
    }

    // ---- B fill: 128 rows x 16 uint4 chunks per image (2048 over 8 iters)
    #pragma unroll
    for (int it = 0; it < 8; it++) {
        int idx = tid + 256 * it;
        int row = idx >> 4, ch = idx & 15;
        uint32_t off = (uint32_t)row * STRB + ch * 16;
        *(uint4*)(smem + SM_BHI + off) = __ldg(((const uint4*)wbhi) + idx);
        *(uint4*)(smem + SM_BLO + off) = __ldg(((const uint4*)wblo) + idx);
    }
    __syncthreads();

    const int w = tid >> 5, lane = tid & 31;
    const int r0 = (w & 1) * 32;      // warp row offset
    const int c0 = (w >> 1) * 32;     // warp col offset
    const int g = lane >> 3, r = lane & 7;
    const int arow = r + ((g & 1) << 3), acolb = ((g >> 1) << 3) * 2;  // A: m0-7/m8-15 x k0/k8
    const int brow = r + ((g >> 1) << 3), bcolb = ((g & 1) << 3) * 2;  // B: n0-7/n8-15 x k0/k8

    float acc[2][4][4];
    #pragma unroll
    for (int mt = 0; mt < 2; mt++)
        #pragma unroll
        for (int nf = 0; nf < 4; nf++)
            #pragma unroll
            for (int c = 0; c < 4; c++) acc[mt][nf][c] = 0.f;

    #pragma unroll
    for (int kk = 0; kk < 8; kk++) {
        uint32_t ahi[2][4], alo[2][4];
        #pragma unroll
        for (int mt = 0; mt < 2; mt++) {
            uint32_t aa = sb + SM_AHI + (uint32_t)(r0 + mt * 16 + arow) * STRB
                        + kk * 32 + acolb;
            ldmx4(ahi[mt], aa);
            ldmx4(alo[mt], aa + (SM_ALO - SM_AHI));
        }
        uint32_t bhi[2][4], blo[2][4];
        #pragma unroll
        for (int nt = 0; nt < 2; nt++) {
            uint32_t ba = sb + SM_BHI + (uint32_t)(c0 + nt * 16 + brow) * STRB
                        + kk * 32 + bcolb;
            ldmx4(bhi[nt], ba);
            ldmx4(blo[nt], ba + (SM_BLO - SM_BHI));
        }
        #pragma unroll
        for (int mt = 0; mt < 2; mt++)
            #pragma unroll
            for (int nt = 0; nt < 2; nt++)
                #pragma unroll
                for (int h = 0; h < 2; h++) {
                    float* c = acc[mt][nt * 2 + h];
                    mma_bf16(c, ahi[mt], &bhi[nt][2 * h]);
                    mma_bf16(c, ahi[mt], &blo[nt][2 * h]);
                    mma_bf16(c, alo[mt], &bhi[nt][2 * h]);
                }
    }

    // ---- Epilogue: bias (node tiles) + fp16 store (__half2, col even -> 4B aligned)
    #pragma unroll
    for (int mt = 0; mt < 2; mt++) {
        int row0 = m0 + r0 + mt * 16 + (lane >> 2);
        #pragma unroll
        for (int nf = 0; nf < 4; nf++) {
            int col = c0 + nf * 8 + 2 * (lane & 3);
            float2 bi = is_node ? *(const float2*)(g_bias + col)
                                : make_float2(0.f, 0.f);
            if (row0 < nrows) {
                __half2 o = __floats2half2_rn(acc[mt][nf][0] + bi.x,
                                              acc[mt][nf][1] + bi.y);
                *(__half2*)(outp + (size_t)row0 * 128 + col) = o;
            }
            if (row0 + 8 < nrows) {
                __half2 o = __floats2half2_rn(acc[mt][nf][2] + bi.x,
                                              acc[mt][nf][3] + bi.y);
                *(__half2*)(outp + (size_t)(row0 + 8) * 128 + col) = o;
            }
        }
    }
}

// ---------------------------------------------------------------------------
// Kernel 3: warp-per-edge: emb_i = relu(yd_i + zsum_e), max-min pool, score.
// ---------------------------------------------------------------------------
__global__ void edge_kernel(const int* __restrict__ node_ids,
                            const float* __restrict__ w_score,
                            const float* __restrict__ b_score,
                            float* __restrict__ out) {
    int gw   = (blockIdx.x * blockDim.x + threadIdx.x) >> 5;
    int lane = threadIdx.x & 31;
    if (gw >= NUM_EDGES) return;

    const int4* ids4 = (const int4*)(node_ids + gw * INC);
    int4 i0 = __ldg(ids4 + 0), i1 = __ldg(ids4 + 1), i2 = __ldg(ids4 + 2);
    int ids[INC] = {i0.x, i0.y, i0.z, i0.w, i1.x, i1.y, i1.z, i1.w,
                    i2.x, i2.y, i2.z, i2.w};

    float4 zs = h4_to_f4(__ldg(((const uint2*)(g_zsum + (size_t)gw * 128)) + lane));

    float4 mx = make_float4(-1e30f, -1e30f, -1e30f, -1e30f);
    float4 mn = make_float4( 1e30f,  1e30f,  1e30f,  1e30f);
    #pragma unroll
    for (int i = 0; i < INC; i++) {
        float4 yd = h4_to_f4(__ldg(((const uint2*)(g_yd + (size_t)ids[i] * 128)) + lane));
        float vx = fmaxf(yd.x + zs.x, 0.f);
        float vy = fmaxf(yd.y + zs.y, 0.f);
        float vz = fmaxf(yd.z + zs.z, 0.f);
        float vw = fmaxf(yd.w + zs.w, 0.f);
        mx.x = fmaxf(mx.x, vx); mn.x = fminf(mn.x, vx);
        mx.y = fmaxf(mx.y, vy); mn.y = fminf(mn.y, vy);
        mx.z = fmaxf(mx.z, vz); mn.z = fminf(mn.z, vz);
        mx.w = fmaxf(mx.w, vw); mn.w = fminf(mn.w, vw);
    }

    float4 w = __ldg(((const float4*)w_score) + lane);
    float p = (mx.x - mn.x) * w.x + (mx.y - mn.y) * w.y
            + (mx.z - mn.z) * w.z + (mx.w - mn.w) * w.w;
    #pragma unroll
    for (int o = 16; o > 0; o >>= 1)
        p += __shfl_xor_sync(0xffffffffu, p, o);
    if (lane == 0) out[gw] = p + __ldg(b_score);
}

// ---------------------------------------------------------------------------
extern "C" void kernel_launch(void* const* d_in, const int* in_sizes, int n_in,
                              void* d_out, int out_size) {
    const float* x    = (const float*)d_in[0];
    const int*   hidx = (const int*)  d_in[1];   // (2, 600000): row0 = node_ids
    const float* Ws   = (const float*)d_in[2];
    const float* bs   = (const float*)d_in[3];
    const float* Wh   = (const float*)d_in[4];
    const float* bh   = (const float*)d_in[5];
    const float* Wsc  = (const float*)d_in[6];
    const float* bsc  = (const float*)d_in[7];
    float* out = (float*)d_out;

    cudaFuncSetAttribute(mma_kernel, cudaFuncAttributeMaxDynamicSharedMemorySize, SM_TOTAL);

    prep_kernel<<<128, 256>>>(Ws, bs, Wh, bh);
    xsum_kernel<<<(NUM_EDGES * 32 + 255) / 256, 256>>>(hidx, x);
    mma_kernel<<<N_NODE_T + N_EDGE_T, 256, SM_TOTAL>>>(x);
    edge_kernel<<<(NUM_EDGES * 32 + 255) / 256, 256>>>(hidx, Wsc, bsc, out);
}

// round 16
// speedup vs baseline: 1.3330x; 1.0717x over previous
#include <cuda_runtime.h>
#include <cuda_bf16.h>
#include <cuda_fp16.h>
#include <cstdint>

#define NUM_NODES 100000
#define NUM_EDGES 50000
#define INC 12
#define N_NODE_T 1563   // ceil(100000/64)
#define N_EDGE_T 782    // ceil(50000/64)

// Scratch:
__device__ __align__(16) __half g_yd[(size_t)NUM_NODES * 128];   // x(Ws-Wh)^T + bias (fp16)
__device__ __align__(16) float  g_xsum[(size_t)NUM_EDGES * 128]; // per-edge sum of x rows
__device__ __align__(16) __half g_zsum[(size_t)NUM_EDGES * 128]; // xsum·Wh^T (fp16)
// bf16 hi/lo weight images: [0:16384)=Wd=(Ws-Wh), [16384:32768)=Wh  (row n, col k)
__device__ __align__(16) __nv_bfloat16 g_bhi[2 * 16384];
__device__ __align__(16) __nv_bfloat16 g_blo[2 * 16384];
__device__ __align__(16) float g_bias[128];

__device__ __forceinline__ uint32_t smem_u32(const void* p) {
    uint32_t a;
    asm("{ .reg .u64 t; cvta.to.shared.u64 t, %1; cvt.u32.u64 %0, t; }" : "=r"(a) : "l"(p));
    return a;
}
__device__ __forceinline__ void ldmx4(uint32_t* r, uint32_t addr) {
    asm volatile("ldmatrix.sync.aligned.m8n8.x4.shared.b16 {%0,%1,%2,%3}, [%4];"
        : "=r"(r[0]), "=r"(r[1]), "=r"(r[2]), "=r"(r[3]) : "r"(addr));
}
__device__ __forceinline__ void mma_bf16(float* c, const uint32_t* a, const uint32_t* b) {
    asm volatile("mma.sync.aligned.m16n8k16.row.col.f32.bf16.bf16.f32 "
        "{%0,%1,%2,%3}, {%4,%5,%6,%7}, {%8,%9}, {%0,%1,%2,%3};"
        : "+f"(c[0]), "+f"(c[1]), "+f"(c[2]), "+f"(c[3])
        : "r"(a[0]), "r"(a[1]), "r"(a[2]), "r"(a[3]), "r"(b[0]), "r"(b[1]));
}
__device__ __forceinline__ uint32_t bpack(float e0, float e1) {  // e0 -> low half
    uint32_t r;
    asm("cvt.rn.bf16x2.f32 %0, %1, %2;" : "=r"(r) : "f"(e1), "f"(e0));
    return r;
}

// SMEM: padded row stride 272 B (ldmatrix conflict-free, 16B-aligned rows)
// Tile M=64 x N=128: total 104448 B -> 2 CTAs/SM.
#define STRB 272
#define SM_AHI 0
#define SM_ALO (64 * STRB)               // 17408
#define SM_BHI (2 * 64 * STRB)           // 34816
#define SM_BLO (SM_BHI + 128 * STRB)     // 69632
#define SM_TOTAL (SM_BLO + 128 * STRB)   // 104448

// ---------------------------------------------------------------------------
// Kernel 0: weights -> bf16 hi/lo images + fused bias
// ---------------------------------------------------------------------------
__global__ void prep_kernel(const float* __restrict__ Ws, const float* __restrict__ bs,
                            const float* __restrict__ Wh, const float* __restrict__ bh) {
    int idx = blockIdx.x * blockDim.x + threadIdx.x;   // 0..32767
    int img = idx >> 14, n = (idx >> 7) & 127, k = idx & 127;
    float v = img ? Wh[n * 128 + k] : (Ws[n * 128 + k] - Wh[n * 128 + k]);
    __nv_bfloat16 hi = __float2bfloat16_rn(v);
    g_bhi[idx] = hi;
    g_blo[idx] = __float2bfloat16_rn(v - __bfloat162float(hi));
    if (idx < 128) g_bias[idx] = bs[idx] + bh[idx];
}

// ---------------------------------------------------------------------------
// Kernel 1: warp-per-edge xsum_e = sum of the 12 incident x rows (fp32)
// ---------------------------------------------------------------------------
__global__ void xsum_kernel(const int* __restrict__ node_ids,
                            const float* __restrict__ x) {
    int gw   = (blockIdx.x * blockDim.x + threadIdx.x) >> 5;
    int lane = threadIdx.x & 31;
    if (gw >= NUM_EDGES) return;

    const int4* ids4 = (const int4*)(node_ids + gw * INC);
    int4 i0 = __ldg(ids4 + 0), i1 = __ldg(ids4 + 1), i2 = __ldg(ids4 + 2);
    int ids[INC] = {i0.x, i0.y, i0.z, i0.w, i1.x, i1.y, i1.z, i1.w,
                    i2.x, i2.y, i2.z, i2.w};

    float4 s = make_float4(0.f, 0.f, 0.f, 0.f);
    #pragma unroll
    for (int i = 0; i < INC; i++) {
        float4 v = __ldg(((const float4*)(x + (size_t)ids[i] * 128)) + lane);
        s.x += v.x; s.y += v.y; s.z += v.z; s.w += v.w;
    }
    ((float4*)(g_xsum + (size_t)gw * 128))[lane] = s;
}

// ---------------------------------------------------------------------------
// Kernel 2: merged split-bf16 mma.sync GEMM, occ 2. CTA tile M=64 x N=128.
//   blockIdx < N_NODE_T: node tile — in=x, out=g_yd, B=Wd, +bias
//   else:                edge tile — in=g_xsum, out=g_zsum, B=Wh, bias 0
// ---------------------------------------------------------------------------
__global__ void __launch_bounds__(256, 2) mma_kernel(const float* __restrict__ x) {
    extern __shared__ char smem[];
    const uint32_t sb = smem_u32(smem);
    const int tid = threadIdx.x;
    const bool is_node = blockIdx.x < N_NODE_T;
    const int m0 = (is_node ? blockIdx.x : blockIdx.x - N_NODE_T) * 64;
    const int nrows = is_node ? NUM_NODES : NUM_EDGES;
    const float* in = is_node ? x : g_xsum;
    __half* outp = is_node ? g_yd : g_zsum;
    const __nv_bfloat16* wbhi = g_bhi + (is_node ? 0 : 16384);
    const __nv_bfloat16* wblo = g_blo + (is_node ? 0 : 16384);

    // ---- A fill: 64 rows x 32 float4 (2048 over 8 iters), split bf16 hi/lo
    #pragma unroll
    for (int it = 0; it < 8; it++) {
        int idx = tid + 256 * it;
        int row = idx >> 5, c4 = idx & 31;
        int gm = m0 + row;
        float4 v = make_float4(0.f, 0.f, 0.f, 0.f);
        if (gm < nrows)
            v = __ldg(((const float4*)(in + (size_t)gm * 128)) + c4);
        __nv_bfloat16 h0 = __float2bfloat16_rn(v.x), h1 = __float2bfloat16_rn(v.y);
        __nv_bfloat16 h2 = __float2bfloat16_rn(v.z), h3 = __float2bfloat16_rn(v.w);
        uint32_t hi01 = ((uint32_t)__bfloat16_as_ushort(h1) << 16) | __bfloat16_as_ushort(h0);
        uint32_t hi23 = ((uint32_t)__bfloat16_as_ushort(h3) << 16) | __bfloat16_as_ushort(h2);
        uint32_t lo01 = bpack(v.x - __bfloat162float(h0), v.y - __bfloat162float(h1));
        uint32_t lo23 = bpack(v.z - __bfloat162float(h2), v.w - __bfloat162float(h3));
        uint32_t off = (uint32_t)row * STRB + c4 * 8;
        *(uint2*)(smem + SM_AHI + off) = make_uint2(hi01, hi23);
        *(uint2*)(smem + SM_ALO + off) = make_uint2(lo01, lo23);
    }

    // ---- B fill: 128 rows x 16 uint4 chunks per image (2048 over 8 iters)
    #pragma unroll
    for (int it = 0; it < 8; it++) {
        int idx = tid + 256 * it;
        int row = idx >> 4, ch = idx & 15;
        uint32_t off = (uint32_t)row * STRB + ch * 16;
        *(uint4*)(smem + SM_BHI + off) = __ldg(((const uint4*)wbhi) + idx);
        *(uint4*)(smem + SM_BLO + off) = __ldg(((const uint4*)wblo) + idx);
    }
    __syncthreads();

    const int w = tid >> 5, lane = tid & 31;
    const int r0 = (w & 1) * 32;      // warp row offset
    const int c0 = (w >> 1) * 32;     // warp col offset
    const int g = lane >> 3, r = lane & 7;
    const int arow = r + ((g & 1) << 3), acolb = ((g >> 1) << 3) * 2;  // A: m0-7/m8-15 x k0/k8
    const int brow = r + ((g >> 1) << 3), bcolb = ((g & 1) << 3) * 2;  // B: n0-7/n8-15 x k0/k8

    float acc[2][4][4];
    #pragma unroll
    for (int mt = 0; mt < 2; mt++)
        #pragma unroll
        for (int nf = 0; nf < 4; nf++)
            #pragma unroll
            for (int c = 0; c < 4; c++) acc[mt][nf][c] = 0.f;

    #pragma unroll
    for (int kk = 0; kk < 8; kk++) {
        uint32_t ahi[2][4], alo[2][4];
        #pragma unroll
        for (int mt = 0; mt < 2; mt++) {
            uint32_t aa = sb + SM_AHI + (uint32_t)(r0 + mt * 16 + arow) * STRB
                        + kk * 32 + acolb;
            ldmx4(ahi[mt], aa);
            ldmx4(alo[mt], aa + (SM_ALO - SM_AHI));
        }
        uint32_t bhi[2][4], blo[2][4];
        #pragma unroll
        for (int nt = 0; nt < 2; nt++) {
            uint32_t ba = sb + SM_BHI + (uint32_t)(c0 + nt * 16 + brow) * STRB
                        + kk * 32 + bcolb;
            ldmx4(bhi[nt], ba);
            ldmx4(blo[nt], ba + (SM_BLO - SM_BHI));
        }
        #pragma unroll
        for (int mt = 0; mt < 2; mt++)
            #pragma unroll
            for (int nt = 0; nt < 2; nt++)
                #pragma unroll
                for (int h = 0; h < 2; h++) {
                    float* c = acc[mt][nt * 2 + h];
                    mma_bf16(c, ahi[mt], &bhi[nt][2 * h]);
                    mma_bf16(c, ahi[mt], &blo[nt][2 * h]);
                    mma_bf16(c, alo[mt], &bhi[nt][2 * h]);
                }
    }

    // ---- Epilogue: bias (node tiles) + fp16 store (__half2, col even -> 4B aligned)
    #pragma unroll
    for (int mt = 0; mt < 2; mt++) {
        int row0 = m0 + r0 + mt * 16 + (lane >> 2);
        #pragma unroll
        for (int nf = 0; nf < 4; nf++) {
            int col = c0 + nf * 8 + 2 * (lane & 3);
            float2 bi = is_node ? *(const float2*)(g_bias + col)
                                : make_float2(0.f, 0.f);
            if (row0 < nrows) {
                __half2 o = __floats2half2_rn(acc[mt][nf][0] + bi.x,
                                              acc[mt][nf][1] + bi.y);
                *(__half2*)(outp + (size_t)row0 * 128 + col) = o;
            }
            if (row0 + 8 < nrows) {
                __half2 o = __floats2half2_rn(acc[mt][nf][2] + bi.x,
                                              acc[mt][nf][3] + bi.y);
                *(__half2*)(outp + (size_t)(row0 + 8) * 128 + col) = o;
            }
        }
    }
}

// ---------------------------------------------------------------------------
// Kernel 3: warp-per-edge pooling. Running max/min over the 12 yd rows in
// NATIVE half2 (exact comparisons, no adds/relu in the loop — zs is constant
// per edge so max_i(yd_i+zs) = (max_i yd_i)+zs, and relu commutes with
// max/min). Post-loop: convert to fp32 (exact), add zs (exact fp32 add of
// halfs), relu, diff, dot. Bitwise identical to the fp32-loop version.
// ---------------------------------------------------------------------------
__global__ void edge_kernel(const int* __restrict__ node_ids,
                            const float* __restrict__ w_score,
                            const float* __restrict__ b_score,
                            float* __restrict__ out) {
    int gw   = (blockIdx.x * blockDim.x + threadIdx.x) >> 5;
    int lane = threadIdx.x & 31;
    if (gw >= NUM_EDGES) return;

    const int4* ids4 = (const int4*)(node_ids + gw * INC);
    int4 i0 = __ldg(ids4 + 0), i1 = __ldg(ids4 + 1), i2 = __ldg(ids4 + 2);
    int ids[INC] = {i0.x, i0.y, i0.z, i0.w, i1.x, i1.y, i1.z, i1.w,
                    i2.x, i2.y, i2.z, i2.w};

    const char* ydb = (const char*)g_yd;
    // init with incidence 0
    uint2 u0 = __ldg((const uint2*)(ydb + ((uint32_t)ids[0] << 8)) + lane);
    __half2 mxa = *(__half2*)&u0.x, mxb = *(__half2*)&u0.y;
    __half2 mna = mxa, mnb = mxb;

    #pragma unroll
    for (int i = 1; i < INC; i++) {
        uint2 u = __ldg((const uint2*)(ydb + ((uint32_t)ids[i] << 8)) + lane);
        __half2 a = *(__half2*)&u.x, b = *(__half2*)&u.y;
        mxa = __hmax2(mxa, a); mna = __hmin2(mna, a);
        mxb = __hmax2(mxb, b); mnb = __hmin2(mnb, b);
    }

    // zs once per edge
    uint2 uz = __ldg(((const uint2*)(g_zsum + (size_t)gw * 128)) + lane);
    __half2 za = *(__half2*)&uz.x, zb = *(__half2*)&uz.y;
    float2 fza = __half22float2(za), fzb = __half22float2(zb);
    float2 fxa = __half22float2(mxa), fxb = __half22float2(mxb);
    float2 fna = __half22float2(mna), fnb = __half22float2(mnb);

    float hx0 = fmaxf(fxa.x + fza.x, 0.f) - fmaxf(fna.x + fza.x, 0.f);
    float hx1 = fmaxf(fxa.y + fza.y, 0.f) - fmaxf(fna.y + fza.y, 0.f);
    float hx2 = fmaxf(fxb.x + fzb.x, 0.f) - fmaxf(fnb.x + fzb.x, 0.f);
    float hx3 = fmaxf(fxb.y + fzb.y, 0.f) - fmaxf(fnb.y + fzb.y, 0.f);

    float4 w = __ldg(((const float4*)w_score) + lane);
    float p = hx0 * w.x + hx1 * w.y + hx2 * w.z + hx3 * w.w;
    #pragma unroll
    for (int o = 16; o > 0; o >>= 1)
        p += __shfl_xor_sync(0xffffffffu, p, o);
    if (lane == 0) out[gw] = p + __ldg(b_score);
}

// ---------------------------------------------------------------------------
extern "C" void kernel_launch(void* const* d_in, const int* in_sizes, int n_in,
                              void* d_out, int out_size) {
    const float* x    = (const float*)d_in[0];
    const int*   hidx = (const int*)  d_in[1];   // (2, 600000): row0 = node_ids
    const float* Ws   = (const float*)d_in[2];
    const float* bs   = (const float*)d_in[3];
    const float* Wh   = (const float*)d_in[4];
    const float* bh   = (const float*)d_in[5];
    const float* Wsc  = (const float*)d_in[6];
    const float* bsc  = (const float*)d_in[7];
    float* out = (float*)d_out;

    cudaFuncSetAttribute(mma_kernel, cudaFuncAttributeMaxDynamicSharedMemorySize, SM_TOTAL);

    prep_kernel<<<128, 256>>>(Ws, bs, Wh, bh);
    xsum_kernel<<<(NUM_EDGES * 32 + 255) / 256, 256>>>(hidx, x);
    mma_kernel<<<N_NODE_T + N_EDGE_T, 256, SM_TOTAL>>>(x);
    edge_kernel<<<(NUM_EDGES * 32 + 255) / 256, 256>>>(hidx, Wsc, bsc, out);
}